// round 3
// baseline (speedup 1.0000x reference)
#include <cuda_runtime.h>
#include <math.h>
#include <stdint.h>

// ---------------- problem constants ----------------
#define BB   64
#define LL   1024
#define HH   256
#define H2   512
#define CC   111
#define TT   64
#define CIN  1024
#define DD   256
#define KCAT 879
#define KPAD 896
#define NGI  1024
#define KX   623
#define NCH  4

// ---------------- device scratch ----------------
__device__ float g_F[(long)BB * H2 * LL];   // rows 0-255: ctx feats, 256-511: Wf
__device__ float g_scores[BB * LL];
__device__ float g_cov[BB * LL];
__device__ float g_h[2 * BB * HH];
__device__ float g_context[BB * HH];
__device__ float g_gi[BB * NGI];
__device__ float g_xcat[BB * KPAD];
__device__ float g_WcatT[KPAD * NGI];
__device__ float g_gbias[NGI];
__device__ float g_outwT[KX * CC];
__device__ float g_W2[H2 * CIN];
__device__ float g_peB[H2 * LL];
__device__ float g_E[H2 * LL];

__device__ __forceinline__ float ftanh(float x) {
    float y; asm("tanh.approx.f32 %0, %1;" : "=f"(y) : "f"(x)); return y;
}
__device__ __forceinline__ float to_tf32(float x) {
    float y; asm("cvt.rna.tf32.f32 %0, %1;" : "=f"(y) : "f"(x)); return y;
}
__device__ __forceinline__ void mma_tf32(float* d, const uint32_t* a, const uint32_t* b) {
    asm volatile(
        "mma.sync.aligned.m16n8k8.row.col.f32.tf32.tf32.f32 "
        "{%0,%1,%2,%3}, {%4,%5,%6,%7}, {%8,%9}, {%0,%1,%2,%3};\n"
        : "+f"(d[0]), "+f"(d[1]), "+f"(d[2]), "+f"(d[3])
        : "r"(a[0]), "r"(a[1]), "r"(a[2]), "r"(a[3]), "r"(b[0]), "r"(b[1]));
}
__device__ __forceinline__ float pe_val(int l, int o) {
    float f = expf((float)(o & ~1) * (-9.210340371976184f / 512.f));
    float a = (float)l * f;
    return (o & 1) ? cosf(a) : sinf(a);
}

// ---------------- prep ----------------
__global__ void prep_kernel(const float* __restrict__ wih, const float* __restrict__ whh,
                            const float* __restrict__ bih, const float* __restrict__ bhh,
                            const float* __restrict__ outw, const float* __restrict__ convw,
                            const float* __restrict__ convb) {
    const long R1 = (long)KPAD * NGI;
    const long R2 = R1 + NGI;
    const long R3 = R2 + (long)KX * CC;
    const long R4 = R3 + 256L * CIN;
    const long R5 = R4 + (long)H2 * LL;
    const long R6 = R5 + 256L * LL;
    const long ZTOT = 2L*BB*HH + BB*LL + BB*HH + BB*KPAD;
    const long TOTAL = R6 + ZTOT;
    for (long idx = (long)blockIdx.x * blockDim.x + threadIdx.x; idx < TOTAL;
         idx += (long)gridDim.x * blockDim.x) {
        long i = idx;
        if (i < R1) {
            int k = (int)(i >> 10), j = (int)(i & 1023);
            float v = 0.f;
            if (k < KCAT) {
                if (j < 768) {
                    if (k < KX) v = wih[j * KX + k];
                    else if (j < 512) v = whh[j * HH + (k - KX)];
                } else {
                    if (k >= KX) v = whh[(j - 768 + 512) * HH + (k - KX)];
                }
            }
            g_WcatT[i] = v; continue;
        }
        if (i < R2) { int j = (int)(i - R1);
            g_gbias[j] = (j < 512) ? bih[j] + bhh[j] : (j < 768) ? bih[j] : bhh[j - 256];
            continue; }
        if (i < R3) { long p = i - R2; int k = (int)(p / CC), c = (int)(p % CC);
            g_outwT[p] = outw[c * KX + k]; continue; }
        if (i < R4) { long p = i - R3; g_W2[p] = convw[p]; continue; }
        if (i < R5) { long p = i - R4; int o = (int)(p >> 10), l = (int)(p & 1023);
            g_peB[p] = pe_val(l, o) + convb[o]; continue; }
        if (i < R6) { long p = i - R5; int m = (int)(p >> 10), l = (int)(p & 1023);
            g_E[p] = convb[m] + pe_val(l, m); continue; }
        long p = i - R6;
        if (p < 2L*BB*HH) { g_h[p] = 0.f; continue; } p -= 2L*BB*HH;
        if (p < BB*LL) { g_cov[p] = 0.f; continue; } p -= BB*LL;
        if (p < BB*HH) { g_context[p] = 0.f; continue; } p -= BB*HH;
        g_xcat[p] = 0.f;
    }
}

// ---------------- SIMT SGEMM (small prep GEMMs only) ----------------
__global__ __launch_bounds__(256, 2) void sgemm_kernel(
    const float* __restrict__ A, const float* __restrict__ Bg, float* __restrict__ Cg,
    int M, int N, int K, const float* __restrict__ bias) {
    const int bx = blockIdx.x, by = blockIdx.y, b = blockIdx.z;
    const float* Bp = Bg + (long)b * K * N;
    float* Cp = Cg + (long)b * M * N;
    const int tid = threadIdx.x;
    __shared__ float As[8][128];
    __shared__ float Bs[8][128];
    float acc[8][8];
#pragma unroll
    for (int i = 0; i < 8; i++)
#pragma unroll
        for (int j = 0; j < 8; j++) acc[i][j] = 0.f;
    const int m0 = by * 128, n0 = bx * 128;
    const int arow = tid >> 1, acol = (tid & 1) * 4;
    const int brow = tid >> 5, bcol = (tid & 31) * 4;
    const int ty = tid >> 4, tx = tid & 15;
    for (int k0 = 0; k0 < K; k0 += 8) {
        float4 a4 = *(const float4*)&A[(long)(m0 + arow) * K + k0 + acol];
        As[acol + 0][arow] = a4.x; As[acol + 1][arow] = a4.y;
        As[acol + 2][arow] = a4.z; As[acol + 3][arow] = a4.w;
        *(float4*)&Bs[brow][bcol] = *(const float4*)&Bp[(long)(k0 + brow) * N + n0 + bcol];
        __syncthreads();
#pragma unroll
        for (int kk = 0; kk < 8; kk++) {
            float ra[8], rb[8];
#pragma unroll
            for (int i = 0; i < 8; i++) ra[i] = As[kk][ty * 8 + i];
#pragma unroll
            for (int j = 0; j < 8; j++) rb[j] = Bs[kk][tx * 8 + j];
#pragma unroll
            for (int i = 0; i < 8; i++)
#pragma unroll
                for (int j = 0; j < 8; j++) acc[i][j] = fmaf(ra[i], rb[j], acc[i][j]);
        }
        __syncthreads();
    }
#pragma unroll
    for (int i = 0; i < 8; i++) {
        int m = m0 + ty * 8 + i;
        float bia = bias ? bias[m] : 0.f;
#pragma unroll
        for (int j = 0; j < 8; j++)
            Cp[(long)m * N + n0 + tx * 8 + j] = acc[i][j] + bia;
    }
}

// ---------------- TF32 tensor-core main GEMM ----------------
// F[b](512x1024) = W2(512x1024) @ fm[b](1024x1024) + E(512x1024)
#define GM 512
#define GN 1024
#define GK 1024
__global__ __launch_bounds__(256, 2) void mma_gemm_kernel(
    const float* __restrict__ A, const float* __restrict__ Bg,
    float* __restrict__ Cg, const float* __restrict__ Etab) {
    const int tid = threadIdx.x;
    const int bx = blockIdx.x, by = blockIdx.y, b = blockIdx.z;
    const float* Bp = Bg + (long)b * GK * GN;
    float* Cp = Cg + (long)b * GM * GN;
    __shared__ float As[32][132];
    __shared__ float Bs[32][132];
    const int w = tid >> 5, lane = tid & 31;
    const int wm = (w & 3) * 32, wn = (w >> 2) * 64;
    const int m0 = by * 128, n0 = bx * 128;
    const int lg = lane >> 2, lk = lane & 3;

    float acc[2][8][4];
#pragma unroll
    for (int i = 0; i < 2; i++)
#pragma unroll
        for (int j = 0; j < 8; j++)
#pragma unroll
            for (int c = 0; c < 4; c++) acc[i][j][c] = 0.f;

    const int am = tid >> 1, ak = (tid & 1) * 16;
    const int bk = tid >> 3, bn = (tid & 7) * 4;

    float4 ra[4], rb[4];
#pragma unroll
    for (int j = 0; j < 4; j++) {
        ra[j] = *(const float4*)&A[(long)(m0 + am) * GK + ak + j * 4];
        rb[j] = *(const float4*)&Bp[(long)bk * GN + n0 + bn + j * 32];
    }

    for (int kt = 0; kt < GK / 32; kt++) {
        // store current chunk (tf32-rounded)
#pragma unroll
        for (int j = 0; j < 4; j++) {
            As[ak + j * 4 + 0][am] = to_tf32(ra[j].x);
            As[ak + j * 4 + 1][am] = to_tf32(ra[j].y);
            As[ak + j * 4 + 2][am] = to_tf32(ra[j].z);
            As[ak + j * 4 + 3][am] = to_tf32(ra[j].w);
            Bs[bk][bn + j * 32 + 0] = to_tf32(rb[j].x);
            Bs[bk][bn + j * 32 + 1] = to_tf32(rb[j].y);
            Bs[bk][bn + j * 32 + 2] = to_tf32(rb[j].z);
            Bs[bk][bn + j * 32 + 3] = to_tf32(rb[j].w);
        }
        __syncthreads();
        if (kt + 1 < GK / 32) {
            int k0 = (kt + 1) * 32;
#pragma unroll
            for (int j = 0; j < 4; j++) {
                ra[j] = *(const float4*)&A[(long)(m0 + am) * GK + k0 + ak + j * 4];
                rb[j] = *(const float4*)&Bp[(long)(k0 + bk) * GN + n0 + bn + j * 32];
            }
        }
#pragma unroll
        for (int ks = 0; ks < 4; ks++) {
            uint32_t afr[2][4];
#pragma unroll
            for (int tm = 0; tm < 2; tm++) {
                int mm = wm + tm * 16 + lg;
                afr[tm][0] = __float_as_uint(As[ks * 8 + lk][mm]);
                afr[tm][1] = __float_as_uint(As[ks * 8 + lk][mm + 8]);
                afr[tm][2] = __float_as_uint(As[ks * 8 + 4 + lk][mm]);
                afr[tm][3] = __float_as_uint(As[ks * 8 + 4 + lk][mm + 8]);
            }
#pragma unroll
            for (int tn = 0; tn < 8; tn++) {
                uint32_t bfr[2];
                int nn = wn + tn * 8 + lg;
                bfr[0] = __float_as_uint(Bs[ks * 8 + lk][nn]);
                bfr[1] = __float_as_uint(Bs[ks * 8 + 4 + lk][nn]);
                mma_tf32(acc[0][tn], afr[0], bfr);
                mma_tf32(acc[1][tn], afr[1], bfr);
            }
        }
        __syncthreads();
    }
    // epilogue: add E table, store
#pragma unroll
    for (int tm = 0; tm < 2; tm++) {
#pragma unroll
        for (int tn = 0; tn < 8; tn++) {
            int m = m0 + wm + tm * 16 + lg;
            int n = n0 + wn + tn * 8 + 2 * lk;
            long i0 = (long)m * GN + n;
            long i1 = (long)(m + 8) * GN + n;
            float2 e0 = *(const float2*)&Etab[i0];
            float2 e1 = *(const float2*)&Etab[i1];
            *(float2*)&Cp[i0] = make_float2(acc[tm][tn][0] + e0.x, acc[tm][tn][1] + e0.y);
            *(float2*)&Cp[i1] = make_float2(acc[tm][tn][2] + e1.x, acc[tm][tn][3] + e1.y);
        }
    }
}

// ---------------- K1: gate finalize + out_{t-1} + attention scores ----------------
__global__ __launch_bounds__(256) void score_kernel(
    int t, int nch,
    const float* __restrict__ count,
    const float* __restrict__ attn_v, const float* __restrict__ attn_vb,
    const float* __restrict__ cov_w, const float* __restrict__ cov_b,
    const float* __restrict__ out_b, float* __restrict__ d_out) {
    const int b = blockIdx.y, cx = blockIdx.x, tid = threadIdx.x;
    float hn = 0.f;
    if (t > 0) {
        const float* gi = g_gi + b * NGI;
        float gr = gi[tid], gz = gi[256 + tid], gin = gi[512 + tid], ghn = gi[768 + tid];
        float hold = g_h[((t - 1) & 1) * BB * HH + b * HH + tid];
        float r = 1.f / (1.f + expf(-gr));
        float z = 1.f / (1.f + expf(-gz));
        float n = tanhf(gin + r * ghn);
        hn = (1.f - z) * n + z * hold;
    }

    if (cx == nch) {  // aux block: write h_t, emit out_{t-1}
        __shared__ float s_x2[640];
        if (t > 0) {
            g_h[(t & 1) * BB * HH + b * HH + tid] = hn;
            s_x2[tid] = hn;
            s_x2[256 + tid] = g_context[b * HH + tid];
            if (tid < CC) s_x2[512 + tid] = count[b * CC + tid];
            __syncthreads();
            if (tid < CC) {
                float acc = out_b[tid];
#pragma unroll 4
                for (int k = 0; k < KX; k++) acc = fmaf(g_outwT[k * CC + tid], s_x2[k], acc);
                d_out[((long)b * TT + (t - 1)) * CC + tid] = acc;
            }
        }
        return;
    }

    __shared__ float s_base[HH], s_cw[HH], s_v[HH];
    s_base[tid] = cov_b[tid] + hn;
    s_cw[tid] = cov_w[tid];
    s_v[tid] = attn_v[tid];
    __syncthreads();

    const int l = cx * 256 + tid;
    const float cov = g_cov[b * LL + l];
    const float* wf = g_F + ((long)b * H2 + 256) * LL + l;
    float a0 = attn_vb[0], a1 = 0.f, a2 = 0.f, a3 = 0.f;
#pragma unroll 2
    for (int h = 0; h < HH; h += 4) {
        float w0 = wf[(long)(h + 0) * LL], w1 = wf[(long)(h + 1) * LL];
        float w2 = wf[(long)(h + 2) * LL], w3 = wf[(long)(h + 3) * LL];
        a0 = fmaf(s_v[h + 0], ftanh(fmaf(cov, s_cw[h + 0], w0 + s_base[h + 0])), a0);
        a1 = fmaf(s_v[h + 1], ftanh(fmaf(cov, s_cw[h + 1], w1 + s_base[h + 1])), a1);
        a2 = fmaf(s_v[h + 2], ftanh(fmaf(cov, s_cw[h + 2], w2 + s_base[h + 2])), a2);
        a3 = fmaf(s_v[h + 3], ftanh(fmaf(cov, s_cw[h + 3], w3 + s_base[h + 3])), a3);
    }
    g_scores[b * LL + l] = (a0 + a1) + (a2 + a3);
}

// ---------------- K2: softmax + coverage + context + xcat + gi init ----------------
__global__ __launch_bounds__(256) void ctx_kernel(
    int t, const float* __restrict__ count, const int* __restrict__ target,
    const float* __restrict__ emb) {
    const int b = blockIdx.y, c = blockIdx.x, tid = threadIdx.x;
    const int warp = tid >> 5, lane = tid & 31;
    __shared__ float s_alpha[LL];
    __shared__ float s_red[8];

    float4 sc = ((const float4*)(g_scores + b * LL))[tid];
    float mx = fmaxf(fmaxf(sc.x, sc.y), fmaxf(sc.z, sc.w));
#pragma unroll
    for (int o = 16; o > 0; o >>= 1) mx = fmaxf(mx, __shfl_xor_sync(0xffffffffu, mx, o));
    if (lane == 0) s_red[warp] = mx;
    __syncthreads();
    float M = s_red[0];
#pragma unroll
    for (int w = 1; w < 8; w++) M = fmaxf(M, s_red[w]);
    float e0 = __expf(sc.x - M), e1 = __expf(sc.y - M);
    float e2 = __expf(sc.z - M), e3 = __expf(sc.w - M);
    float sm = e0 + e1 + e2 + e3;
#pragma unroll
    for (int o = 16; o > 0; o >>= 1) sm += __shfl_xor_sync(0xffffffffu, sm, o);
    __syncthreads();
    if (lane == 0) s_red[warp] = sm;
    __syncthreads();
    float S = 0.f;
#pragma unroll
    for (int w = 0; w < 8; w++) S += s_red[w];
    float inv = 1.f / S;
    float4 al = make_float4(e0 * inv, e1 * inv, e2 * inv, e3 * inv);
    ((float4*)s_alpha)[tid] = al;
    if (c == 0) {
        float4 cv = ((float4*)(g_cov + b * LL))[tid];
        cv.x += al.x; cv.y += al.y; cv.z += al.z; cv.w += al.w;
        ((float4*)(g_cov + b * LL))[tid] = cv;
    }
    __syncthreads();

    const float* fb = g_F + (long)b * H2 * LL;
#pragma unroll
    for (int r = 0; r < 4; r++) {
        int d = c * 32 + warp * 4 + r;
        const float4* row = (const float4*)(fb + (long)d * LL);
        float sum = 0.f;
#pragma unroll
        for (int it = 0; it < 8; it++) {
            float4 f = row[it * 32 + lane];
            float4 a4 = ((const float4*)s_alpha)[it * 32 + lane];
            sum = fmaf(f.x, a4.x, sum); sum = fmaf(f.y, a4.y, sum);
            sum = fmaf(f.z, a4.z, sum); sum = fmaf(f.w, a4.w, sum);
        }
#pragma unroll
        for (int o = 16; o > 0; o >>= 1) sum += __shfl_xor_sync(0xffffffffu, sum, o);
        if (lane == 0) {
            g_context[b * HH + d] = sum;
            g_xcat[b * KPAD + 256 + d] = sum;
        }
    }

    if (tid < 128) g_gi[b * NGI + c * 128 + tid] = g_gbias[c * 128 + tid];
    if (c == 1) {
        int y = (t == 0) ? 1 : target[b * TT + (t - 1)];
        g_xcat[b * KPAD + tid] = emb[y * DD + tid];
    }
    if (c == 2 && tid < CC) g_xcat[b * KPAD + 512 + tid] = count[b * CC + tid];
    if (c == 3) g_xcat[b * KPAD + KX + tid] = g_h[(t & 1) * BB * HH + b * HH + tid];
}

// ---------------- K3: GRU gate GEMM (K-split, atomic) ----------------
__global__ __launch_bounds__(256) void gru_gemm_kernel() {
    const int nt = blockIdx.x & 15, ks = blockIdx.x >> 4;
    const int n0 = nt * 64, k0 = ks * 112;
    const int tid = threadIdx.x;
    __shared__ float Xs[8][64];
    __shared__ float Ws[8][64];
    const int ml = tid >> 2, kl = (tid & 3) * 2;
    const int kw = tid >> 5, nn = (tid & 31) * 2;
    const int ty = tid >> 4, tx = tid & 15;
    float acc[4][4];
#pragma unroll
    for (int i = 0; i < 4; i++)
#pragma unroll
        for (int j = 0; j < 4; j++) acc[i][j] = 0.f;

    for (int kt = 0; kt < 14; kt++) {
        const int k = k0 + kt * 8;
        Xs[kl + 0][ml] = g_xcat[ml * KPAD + k + kl + 0];
        Xs[kl + 1][ml] = g_xcat[ml * KPAD + k + kl + 1];
        float2 w2 = *(const float2*)&g_WcatT[(k + kw) * NGI + n0 + nn];
        Ws[kw][nn] = w2.x; Ws[kw][nn + 1] = w2.y;
        __syncthreads();
#pragma unroll
        for (int kk = 0; kk < 8; kk++) {
            float rx[4], rw[4];
#pragma unroll
            for (int i = 0; i < 4; i++) rx[i] = Xs[kk][ty * 4 + i];
#pragma unroll
            for (int j = 0; j < 4; j++) rw[j] = Ws[kk][tx * 4 + j];
#pragma unroll
            for (int i = 0; i < 4; i++)
#pragma unroll
                for (int j = 0; j < 4; j++) acc[i][j] = fmaf(rx[i], rw[j], acc[i][j]);
        }
        __syncthreads();
    }
#pragma unroll
    for (int i = 0; i < 4; i++)
#pragma unroll
        for (int j = 0; j < 4; j++)
            atomicAdd(&g_gi[(ty * 4 + i) * NGI + n0 + tx * 4 + j], acc[i][j]);
}

// ---------------- launch ----------------
extern "C" void kernel_launch(void* const* d_in, const int* in_sizes, int n_in,
                              void* d_out, int out_size) {
    const float* fm      = (const float*)d_in[0];
    const float* count   = (const float*)d_in[1];
    const int*   target  = (const int*)d_in[2];
    const float* conv_w  = (const float*)d_in[3];
    const float* conv_b  = (const float*)d_in[4];
    const float* emb     = (const float*)d_in[5];
    const float* gru_wih = (const float*)d_in[6];
    const float* gru_whh = (const float*)d_in[7];
    const float* gru_bih = (const float*)d_in[8];
    const float* gru_bhh = (const float*)d_in[9];
    const float* attn_w  = (const float*)d_in[10];
    const float* attn_b  = (const float*)d_in[11];
    const float* attn_v  = (const float*)d_in[12];
    const float* attn_vb = (const float*)d_in[13];
    const float* cov_w   = (const float*)d_in[14];
    const float* cov_b   = (const float*)d_in[15];
    const float* out_w   = (const float*)d_in[16];
    const float* out_b   = (const float*)d_in[17];
    float* out = (float*)d_out;

    float *pF, *pW2, *pPeB, *pE;
    cudaGetSymbolAddress((void**)&pF, g_F);
    cudaGetSymbolAddress((void**)&pW2, g_W2);
    cudaGetSymbolAddress((void**)&pPeB, g_peB);
    cudaGetSymbolAddress((void**)&pE, g_E);

    prep_kernel<<<1024, 256>>>(gru_wih, gru_whh, gru_bih, gru_bhh, out_w, conv_w, conv_b);

    // W2 bottom half: attn_w(256x512) @ conv_w(512x1024)
    sgemm_kernel<<<dim3(8, 2, 1), 256>>>(attn_w, conv_w, pW2 + 256 * CIN,
                                         256, CIN, H2, nullptr);
    // E bottom half: attn_w @ (pe+conv_b) + attn_b
    sgemm_kernel<<<dim3(8, 2, 1), 256>>>(attn_w, pPeB, pE + 256 * LL,
                                         256, LL, H2, attn_b);
    // main: g_F[b] = W2 @ fm[b] + E   (tf32 tensor cores)
    mma_gemm_kernel<<<dim3(8, 4, BB), 256>>>(pW2, fm, pF, pE);

    for (int t = 0; t < TT; t++) {
        score_kernel<<<dim3(NCH + 1, BB), 256>>>(t, NCH, count, attn_v, attn_vb,
                                                 cov_w, cov_b, out_b, out);
        ctx_kernel<<<dim3(8, BB), 256>>>(t, count, target, emb);
        gru_gemm_kernel<<<128, 256>>>();
    }
    score_kernel<<<dim3(1, BB), 256>>>(TT, 0, count, attn_v, attn_vb,
                                       cov_w, cov_b, out_b, out);
}

// round 4
// speedup vs baseline: 1.3023x; 1.3023x over previous
#include <cuda_runtime.h>
#include <cuda_bf16.h>
#include <math.h>
#include <stdint.h>

// ---------------- problem constants ----------------
#define BB   64
#define LL   1024
#define HH   256
#define H2   512
#define CC   111
#define TT   64
#define CIN  1024
#define DD   256
#define KCAT 879
#define KPAD 896
#define NGI  1024
#define KX   623
#define NCH  4
#define GM   512
#define GN   1024
#define GK   1024

// ---------------- device scratch ----------------
__device__ float g_F[(long)BB * H2 * LL];   // rows 0-255: ctx feats, 256-511: Wf
__device__ float g_scores[BB * LL];
__device__ float g_cov[BB * LL];
__device__ float g_h[2 * BB * HH];
__device__ float g_context[BB * HH];
__device__ float g_gi[BB * NGI];
__device__ float g_xcat[BB * KPAD];
__device__ float g_WcatT[KPAD * NGI];
__device__ float g_gbias[NGI];
__device__ float g_outwT[KX * CC];
__device__ float g_W2[H2 * CIN];
__device__ float g_peB[H2 * LL];
__device__ float g_E[H2 * LL];
__device__ __nv_bfloat16 g_fmh[(long)BB * CIN * LL];  // bf16 feature map
__device__ __nv_bfloat16 g_W2h[H2 * CIN];             // bf16 combined weights

__device__ __forceinline__ float ftanh(float x) {
    float y; asm("tanh.approx.f32 %0, %1;" : "=f"(y) : "f"(x)); return y;
}
__device__ __forceinline__ float pe_val(int l, int o) {
    float f = expf((float)(o & ~1) * (-9.210340371976184f / 512.f));
    float a = (float)l * f;
    return (o & 1) ? cosf(a) : sinf(a);
}
__device__ __forceinline__ uint32_t s2u(const void* p) {
    return (uint32_t)__cvta_generic_to_shared(p);
}
__device__ __forceinline__ void ldsm4(uint32_t* r, uint32_t a) {
    asm volatile("ldmatrix.sync.aligned.m8n8.x4.shared.b16 {%0,%1,%2,%3}, [%4];"
                 : "=r"(r[0]), "=r"(r[1]), "=r"(r[2]), "=r"(r[3]) : "r"(a));
}
__device__ __forceinline__ void ldsm4t(uint32_t* r, uint32_t a) {
    asm volatile("ldmatrix.sync.aligned.m8n8.x4.trans.shared.b16 {%0,%1,%2,%3}, [%4];"
                 : "=r"(r[0]), "=r"(r[1]), "=r"(r[2]), "=r"(r[3]) : "r"(a));
}
__device__ __forceinline__ void mma_bf16(float* d, const uint32_t* a, const uint32_t* b) {
    asm volatile(
        "mma.sync.aligned.m16n8k16.row.col.f32.bf16.bf16.f32 "
        "{%0,%1,%2,%3}, {%4,%5,%6,%7}, {%8,%9}, {%0,%1,%2,%3};\n"
        : "+f"(d[0]), "+f"(d[1]), "+f"(d[2]), "+f"(d[3])
        : "r"(a[0]), "r"(a[1]), "r"(a[2]), "r"(a[3]), "r"(b[0]), "r"(b[1]));
}

// ---------------- prep ----------------
__global__ void prep_kernel(const float* __restrict__ wih, const float* __restrict__ whh,
                            const float* __restrict__ bih, const float* __restrict__ bhh,
                            const float* __restrict__ outw, const float* __restrict__ convw,
                            const float* __restrict__ convb) {
    const long R1 = (long)KPAD * NGI;
    const long R2 = R1 + NGI;
    const long R3 = R2 + (long)KX * CC;
    const long R4 = R3 + 256L * CIN;
    const long R5 = R4 + (long)H2 * LL;
    const long R6 = R5 + 256L * LL;
    const long ZTOT = 2L*BB*HH + BB*LL + BB*HH + BB*KPAD;
    const long TOTAL = R6 + ZTOT;
    for (long idx = (long)blockIdx.x * blockDim.x + threadIdx.x; idx < TOTAL;
         idx += (long)gridDim.x * blockDim.x) {
        long i = idx;
        if (i < R1) {
            int k = (int)(i >> 10), j = (int)(i & 1023);
            float v = 0.f;
            if (k < KCAT) {
                if (j < 768) {
                    if (k < KX) v = wih[j * KX + k];
                    else if (j < 512) v = whh[j * HH + (k - KX)];
                } else {
                    if (k >= KX) v = whh[(j - 768 + 512) * HH + (k - KX)];
                }
            }
            g_WcatT[i] = v; continue;
        }
        if (i < R2) { int j = (int)(i - R1);
            g_gbias[j] = (j < 512) ? bih[j] + bhh[j] : (j < 768) ? bih[j] : bhh[j - 256];
            continue; }
        if (i < R3) { long p = i - R2; int k = (int)(p / CC), c = (int)(p % CC);
            g_outwT[p] = outw[c * KX + k]; continue; }
        if (i < R4) { long p = i - R3; g_W2[p] = convw[p]; continue; }
        if (i < R5) { long p = i - R4; int o = (int)(p >> 10), l = (int)(p & 1023);
            g_peB[p] = pe_val(l, o) + convb[o]; continue; }
        if (i < R6) { long p = i - R5; int m = (int)(p >> 10), l = (int)(p & 1023);
            g_E[p] = convb[m] + pe_val(l, m); continue; }
        long p = i - R6;
        if (p < 2L*BB*HH) { g_h[p] = 0.f; continue; } p -= 2L*BB*HH;
        if (p < BB*LL) { g_cov[p] = 0.f; continue; } p -= BB*LL;
        if (p < BB*HH) { g_context[p] = 0.f; continue; } p -= BB*HH;
        g_xcat[p] = 0.f;
    }
}

// ---------------- fp32 -> bf16 conversion ----------------
__global__ void cvt_kernel(const float* __restrict__ fm) {
    const long N1 = (long)BB * CIN * LL / 4;
    const long N2 = (long)H2 * CIN / 4;
    __nv_bfloat162* fo = (__nv_bfloat162*)g_fmh;
    __nv_bfloat162* wo = (__nv_bfloat162*)g_W2h;
    for (long i = (long)blockIdx.x * blockDim.x + threadIdx.x; i < N1 + N2;
         i += (long)gridDim.x * blockDim.x) {
        if (i < N1) {
            float4 v = ((const float4*)fm)[i];
            fo[2 * i]     = __floats2bfloat162_rn(v.x, v.y);
            fo[2 * i + 1] = __floats2bfloat162_rn(v.z, v.w);
        } else {
            long j = i - N1;
            float4 v = ((const float4*)g_W2)[j];
            wo[2 * j]     = __floats2bfloat162_rn(v.x, v.y);
            wo[2 * j + 1] = __floats2bfloat162_rn(v.z, v.w);
        }
    }
}

// ---------------- SIMT SGEMM (small prep GEMMs only) ----------------
__global__ __launch_bounds__(256, 2) void sgemm_kernel(
    const float* __restrict__ A, const float* __restrict__ Bg, float* __restrict__ Cg,
    int M, int N, int K, const float* __restrict__ bias) {
    const int bx = blockIdx.x, by = blockIdx.y, b = blockIdx.z;
    const float* Bp = Bg + (long)b * K * N;
    float* Cp = Cg + (long)b * M * N;
    const int tid = threadIdx.x;
    __shared__ float As[8][128];
    __shared__ float Bs[8][128];
    float acc[8][8];
#pragma unroll
    for (int i = 0; i < 8; i++)
#pragma unroll
        for (int j = 0; j < 8; j++) acc[i][j] = 0.f;
    const int m0 = by * 128, n0 = bx * 128;
    const int arow = tid >> 1, acol = (tid & 1) * 4;
    const int brow = tid >> 5, bcol = (tid & 31) * 4;
    const int ty = tid >> 4, tx = tid & 15;
    for (int k0 = 0; k0 < K; k0 += 8) {
        float4 a4 = *(const float4*)&A[(long)(m0 + arow) * K + k0 + acol];
        As[acol + 0][arow] = a4.x; As[acol + 1][arow] = a4.y;
        As[acol + 2][arow] = a4.z; As[acol + 3][arow] = a4.w;
        *(float4*)&Bs[brow][bcol] = *(const float4*)&Bp[(long)(k0 + brow) * N + n0 + bcol];
        __syncthreads();
#pragma unroll
        for (int kk = 0; kk < 8; kk++) {
            float ra[8], rb[8];
#pragma unroll
            for (int i = 0; i < 8; i++) ra[i] = As[kk][ty * 8 + i];
#pragma unroll
            for (int j = 0; j < 8; j++) rb[j] = Bs[kk][tx * 8 + j];
#pragma unroll
            for (int i = 0; i < 8; i++)
#pragma unroll
                for (int j = 0; j < 8; j++) acc[i][j] = fmaf(ra[i], rb[j], acc[i][j]);
        }
        __syncthreads();
    }
#pragma unroll
    for (int i = 0; i < 8; i++) {
        int m = m0 + ty * 8 + i;
        float bia = bias ? bias[m] : 0.f;
#pragma unroll
        for (int j = 0; j < 8; j++)
            Cp[(long)m * N + n0 + tx * 8 + j] = acc[i][j] + bia;
    }
}

// ---------------- bf16 tensor-core main GEMM ----------------
// F[b](512x1024) = W2h(512x1024) @ fmh[b](1024x1024) + E
__global__ __launch_bounds__(256, 2) void mma_gemm_kernel(
    const __nv_bfloat16* __restrict__ A, const __nv_bfloat16* __restrict__ Bg,
    float* __restrict__ Cg, const float* __restrict__ Etab) {
    const int tid = threadIdx.x;
    const int bx = blockIdx.x, by = blockIdx.y, b = blockIdx.z;
    const __nv_bfloat16* Bp = Bg + (long)b * GK * GN;
    float* Cp = Cg + (long)b * GM * GN;
    __shared__ __nv_bfloat16 As[128][40];    // [m][k] pad stride 40 (20 banks)
    __shared__ __nv_bfloat16 Bs[32][136];    // [k][n] pad stride 136 (4 banks)
    const int w = tid >> 5, lane = tid & 31;
    const int wm = (w & 3) * 32, wn = (w >> 2) * 64;
    const int m0 = by * 128, n0 = bx * 128;
    const int lg = lane >> 2, lk = lane & 3;

    float acc[2][8][4];
#pragma unroll
    for (int i = 0; i < 2; i++)
#pragma unroll
        for (int j = 0; j < 8; j++)
#pragma unroll
            for (int c = 0; c < 4; c++) acc[i][j][c] = 0.f;

    const int ar = tid >> 1, ac = (tid & 1) * 16;   // A: 128 rows x 32 cols
    const int br = tid >> 3, bc = (tid & 7) * 16;   // B: 32 rows x 128 cols

    // per-lane ldmatrix base addresses
    const uint32_t aAddr0 = s2u(&As[wm + (lane & 15)][(lane >> 4) * 8]);
    const uint32_t bAddr0 = s2u(&Bs[lane & 15][wn + (lane >> 4) * 8]);

    uint4 ra0, ra1, rb0, rb1;
    {
        const uint4* pa = (const uint4*)(A + (long)(m0 + ar) * GK + ac);
        const uint4* pb = (const uint4*)(Bp + (long)br * GN + n0 + bc);
        ra0 = pa[0]; ra1 = pa[1];
        rb0 = pb[0]; rb1 = pb[1];
    }

    for (int kt = 0; kt < GK / 32; kt++) {
        *(uint4*)&As[ar][ac]     = ra0;
        *(uint4*)&As[ar][ac + 8] = ra1;
        *(uint4*)&Bs[br][bc]     = rb0;
        *(uint4*)&Bs[br][bc + 8] = rb1;
        __syncthreads();
        if (kt + 1 < GK / 32) {
            int k0 = (kt + 1) * 32;
            const uint4* pa = (const uint4*)(A + (long)(m0 + ar) * GK + k0 + ac);
            const uint4* pb = (const uint4*)(Bp + (long)(k0 + br) * GN + n0 + bc);
            ra0 = pa[0]; ra1 = pa[1];
            rb0 = pb[0]; rb1 = pb[1];
        }
#pragma unroll
        for (int ks = 0; ks < 2; ks++) {
            uint32_t af[2][4], bf[4][4];
#pragma unroll
            for (int tm = 0; tm < 2; tm++)
                ldsm4(af[tm], aAddr0 + (tm * 16 * 40 + ks * 16) * 2);
#pragma unroll
            for (int p = 0; p < 4; p++)
                ldsm4t(bf[p], bAddr0 + (ks * 16 * 136 + p * 16) * 2);
#pragma unroll
            for (int tn = 0; tn < 8; tn++) {
                mma_bf16(acc[0][tn], af[0], &bf[tn >> 1][(tn & 1) * 2]);
                mma_bf16(acc[1][tn], af[1], &bf[tn >> 1][(tn & 1) * 2]);
            }
        }
        __syncthreads();
    }
    // epilogue: add E table, store fp32
#pragma unroll
    for (int tm = 0; tm < 2; tm++) {
#pragma unroll
        for (int tn = 0; tn < 8; tn++) {
            int m = m0 + wm + tm * 16 + lg;
            int n = n0 + wn + tn * 8 + 2 * lk;
            long i0 = (long)m * GN + n;
            long i1 = (long)(m + 8) * GN + n;
            float2 e0 = *(const float2*)&Etab[i0];
            float2 e1 = *(const float2*)&Etab[i1];
            *(float2*)&Cp[i0] = make_float2(acc[tm][tn][0] + e0.x, acc[tm][tn][1] + e0.y);
            *(float2*)&Cp[i1] = make_float2(acc[tm][tn][2] + e1.x, acc[tm][tn][3] + e1.y);
        }
    }
}

// ---------------- K1: gate finalize + out_{t-1} + attention scores ----------------
__global__ __launch_bounds__(256) void score_kernel(
    int t, int nch,
    const float* __restrict__ count,
    const float* __restrict__ attn_v, const float* __restrict__ attn_vb,
    const float* __restrict__ cov_w, const float* __restrict__ cov_b,
    const float* __restrict__ out_b, float* __restrict__ d_out) {
    const int b = blockIdx.y, cx = blockIdx.x, tid = threadIdx.x;
    float hn = 0.f;
    if (t > 0) {
        const float* gi = g_gi + b * NGI;
        float gr = gi[tid], gz = gi[256 + tid], gin = gi[512 + tid], ghn = gi[768 + tid];
        float hold = g_h[((t - 1) & 1) * BB * HH + b * HH + tid];
        float r = 1.f / (1.f + expf(-gr));
        float z = 1.f / (1.f + expf(-gz));
        float n = tanhf(gin + r * ghn);
        hn = (1.f - z) * n + z * hold;
    }

    if (cx == nch) {  // aux block: write h_t, emit out_{t-1}
        __shared__ float s_x2[640];
        if (t > 0) {
            g_h[(t & 1) * BB * HH + b * HH + tid] = hn;
            s_x2[tid] = hn;
            s_x2[256 + tid] = g_context[b * HH + tid];
            if (tid < CC) s_x2[512 + tid] = count[b * CC + tid];
            __syncthreads();
            if (tid < CC) {
                float acc = out_b[tid];
#pragma unroll 4
                for (int k = 0; k < KX; k++) acc = fmaf(g_outwT[k * CC + tid], s_x2[k], acc);
                d_out[((long)b * TT + (t - 1)) * CC + tid] = acc;
            }
        }
        return;
    }

    __shared__ float s_base[HH], s_cw[HH], s_v[HH];
    s_base[tid] = cov_b[tid] + hn;
    s_cw[tid] = cov_w[tid];
    s_v[tid] = attn_v[tid];
    __syncthreads();

    const int l = cx * 256 + tid;
    const float cov = g_cov[b * LL + l];
    const float* wf = g_F + ((long)b * H2 + 256) * LL + l;
    float a = attn_vb[0];
#pragma unroll 8
    for (int h = 0; h < HH; h++)
        a = fmaf(s_v[h], ftanh(fmaf(cov, s_cw[h], wf[(long)h * LL] + s_base[h])), a);
    g_scores[b * LL + l] = a;
}

// ---------------- K2: softmax + coverage + context + xcat + gi init ----------------
__global__ __launch_bounds__(256) void ctx_kernel(
    int t, const float* __restrict__ count, const int* __restrict__ target,
    const float* __restrict__ emb) {
    const int b = blockIdx.y, c = blockIdx.x, tid = threadIdx.x;
    const int warp = tid >> 5, lane = tid & 31;
    __shared__ float s_alpha[LL];
    __shared__ float s_red[8];

    float4 sc = ((const float4*)(g_scores + b * LL))[tid];
    float mx = fmaxf(fmaxf(sc.x, sc.y), fmaxf(sc.z, sc.w));
#pragma unroll
    for (int o = 16; o > 0; o >>= 1) mx = fmaxf(mx, __shfl_xor_sync(0xffffffffu, mx, o));
    if (lane == 0) s_red[warp] = mx;
    __syncthreads();
    float M = s_red[0];
#pragma unroll
    for (int w = 1; w < 8; w++) M = fmaxf(M, s_red[w]);
    float e0 = __expf(sc.x - M), e1 = __expf(sc.y - M);
    float e2 = __expf(sc.z - M), e3 = __expf(sc.w - M);
    float sm = e0 + e1 + e2 + e3;
#pragma unroll
    for (int o = 16; o > 0; o >>= 1) sm += __shfl_xor_sync(0xffffffffu, sm, o);
    __syncthreads();
    if (lane == 0) s_red[warp] = sm;
    __syncthreads();
    float S = 0.f;
#pragma unroll
    for (int w = 0; w < 8; w++) S += s_red[w];
    float inv = 1.f / S;
    float4 al = make_float4(e0 * inv, e1 * inv, e2 * inv, e3 * inv);
    ((float4*)s_alpha)[tid] = al;
    if (c == 0) {
        float4 cv = ((float4*)(g_cov + b * LL))[tid];
        cv.x += al.x; cv.y += al.y; cv.z += al.z; cv.w += al.w;
        ((float4*)(g_cov + b * LL))[tid] = cv;
    }
    __syncthreads();

    const float* fb = g_F + (long)b * H2 * LL;
#pragma unroll
    for (int r = 0; r < 4; r++) {
        int d = c * 32 + warp * 4 + r;
        const float4* row = (const float4*)(fb + (long)d * LL);
        float sum = 0.f;
#pragma unroll
        for (int it = 0; it < 8; it++) {
            float4 f = row[it * 32 + lane];
            float4 a4 = ((const float4*)s_alpha)[it * 32 + lane];
            sum = fmaf(f.x, a4.x, sum); sum = fmaf(f.y, a4.y, sum);
            sum = fmaf(f.z, a4.z, sum); sum = fmaf(f.w, a4.w, sum);
        }
#pragma unroll
        for (int o = 16; o > 0; o >>= 1) sum += __shfl_xor_sync(0xffffffffu, sum, o);
        if (lane == 0) {
            g_context[b * HH + d] = sum;
            g_xcat[b * KPAD + 256 + d] = sum;
        }
    }

    if (tid < 128) g_gi[b * NGI + c * 128 + tid] = g_gbias[c * 128 + tid];
    if (c == 1) {
        int y = (t == 0) ? 1 : target[b * TT + (t - 1)];
        g_xcat[b * KPAD + tid] = emb[y * DD + tid];
    }
    if (c == 2 && tid < CC) g_xcat[b * KPAD + 512 + tid] = count[b * CC + tid];
    if (c == 3) g_xcat[b * KPAD + KX + tid] = g_h[(t & 1) * BB * HH + b * HH + tid];
}

// ---------------- K3: GRU gate GEMM (K-split, atomic) ----------------
__global__ __launch_bounds__(256) void gru_gemm_kernel() {
    const int nt = blockIdx.x & 15, ks = blockIdx.x >> 4;
    const int n0 = nt * 64, k0 = ks * 112;
    const int tid = threadIdx.x;
    __shared__ float Xs[8][64];
    __shared__ float Ws[8][64];
    const int ml = tid >> 2, kl = (tid & 3) * 2;
    const int kw = tid >> 5, nn = (tid & 31) * 2;
    const int ty = tid >> 4, tx = tid & 15;
    float acc[4][4];
#pragma unroll
    for (int i = 0; i < 4; i++)
#pragma unroll
        for (int j = 0; j < 4; j++) acc[i][j] = 0.f;

    for (int kt = 0; kt < 14; kt++) {
        const int k = k0 + kt * 8;
        Xs[kl + 0][ml] = g_xcat[ml * KPAD + k + kl + 0];
        Xs[kl + 1][ml] = g_xcat[ml * KPAD + k + kl + 1];
        float2 w2 = *(const float2*)&g_WcatT[(k + kw) * NGI + n0 + nn];
        Ws[kw][nn] = w2.x; Ws[kw][nn + 1] = w2.y;
        __syncthreads();
#pragma unroll
        for (int kk = 0; kk < 8; kk++) {
            float rx[4], rw[4];
#pragma unroll
            for (int i = 0; i < 4; i++) rx[i] = Xs[kk][ty * 4 + i];
#pragma unroll
            for (int j = 0; j < 4; j++) rw[j] = Ws[kk][tx * 4 + j];
#pragma unroll
            for (int i = 0; i < 4; i++)
#pragma unroll
                for (int j = 0; j < 4; j++) acc[i][j] = fmaf(rx[i], rw[j], acc[i][j]);
        }
        __syncthreads();
    }
#pragma unroll
    for (int i = 0; i < 4; i++)
#pragma unroll
        for (int j = 0; j < 4; j++)
            atomicAdd(&g_gi[(ty * 4 + i) * NGI + n0 + tx * 4 + j], acc[i][j]);
}

// ---------------- launch ----------------
extern "C" void kernel_launch(void* const* d_in, const int* in_sizes, int n_in,
                              void* d_out, int out_size) {
    const float* fm      = (const float*)d_in[0];
    const float* count   = (const float*)d_in[1];
    const int*   target  = (const int*)d_in[2];
    const float* conv_w  = (const float*)d_in[3];
    const float* conv_b  = (const float*)d_in[4];
    const float* emb     = (const float*)d_in[5];
    const float* gru_wih = (const float*)d_in[6];
    const float* gru_whh = (const float*)d_in[7];
    const float* gru_bih = (const float*)d_in[8];
    const float* gru_bhh = (const float*)d_in[9];
    const float* attn_w  = (const float*)d_in[10];
    const float* attn_b  = (const float*)d_in[11];
    const float* attn_v  = (const float*)d_in[12];
    const float* attn_vb = (const float*)d_in[13];
    const float* cov_w   = (const float*)d_in[14];
    const float* cov_b   = (const float*)d_in[15];
    const float* out_w   = (const float*)d_in[16];
    const float* out_b   = (const float*)d_in[17];
    float* out = (float*)d_out;

    float *pF, *pW2, *pPeB, *pE;
    __nv_bfloat16 *pFmh, *pW2h;
    cudaGetSymbolAddress((void**)&pF, g_F);
    cudaGetSymbolAddress((void**)&pW2, g_W2);
    cudaGetSymbolAddress((void**)&pPeB, g_peB);
    cudaGetSymbolAddress((void**)&pE, g_E);
    cudaGetSymbolAddress((void**)&pFmh, g_fmh);
    cudaGetSymbolAddress((void**)&pW2h, g_W2h);

    prep_kernel<<<1024, 256>>>(gru_wih, gru_whh, gru_bih, gru_bhh, out_w, conv_w, conv_b);

    // W2 bottom half: attn_w(256x512) @ conv_w(512x1024)
    sgemm_kernel<<<dim3(8, 2, 1), 256>>>(attn_w, conv_w, pW2 + 256 * CIN,
                                         256, CIN, H2, nullptr);
    // E bottom half: attn_w @ (pe+conv_b) + attn_b
    sgemm_kernel<<<dim3(8, 2, 1), 256>>>(attn_w, pPeB, pE + 256 * LL,
                                         256, LL, H2, attn_b);
    // convert fm and W2 to bf16
    cvt_kernel<<<2048, 256>>>(fm);
    // main: g_F[b] = W2h @ fmh[b] + E   (bf16 tensor cores, fp32 accum)
    mma_gemm_kernel<<<dim3(8, 4, BB), 256>>>(pW2h, pFmh, pF, pE);

    for (int t = 0; t < TT; t++) {
        score_kernel<<<dim3(NCH + 1, BB), 256>>>(t, NCH, count, attn_v, attn_vb,
                                                 cov_w, cov_b, out_b, out);
        ctx_kernel<<<dim3(8, BB), 256>>>(t, count, target, emb);
        gru_gemm_kernel<<<128, 256>>>();
    }
    score_kernel<<<dim3(1, BB), 256>>>(TT, 0, count, attn_v, attn_vb,
                                       cov_w, cov_b, out_b, out);
}

// round 5
// speedup vs baseline: 2.3370x; 1.7945x over previous
#include <cuda_runtime.h>
#include <cuda_bf16.h>
#include <math.h>
#include <stdint.h>

// ---------------- problem constants ----------------
#define BB   64
#define LL   1024
#define HH   256
#define H2   512
#define CC   111
#define TT   64
#define CIN  1024
#define DD   256
#define KCAT 879
#define KPAD 896
#define NGI  1024
#define KX   623
#define GM   512
#define GN   1024
#define GK   1024

// ---------------- device scratch ----------------
__device__ __nv_bfloat16 g_Fh[(long)BB * H2 * LL];  // rows 0-255: ctx feats, 256-511: Wf
__device__ float g_scores[2 * BB * LL];             // two h-half partials
__device__ float g_cov[BB * LL];
__device__ float g_h[2 * BB * HH];
__device__ float g_context[BB * HH];
__device__ float g_gi[BB * NGI];
__device__ float g_xcat[BB * KPAD];
__device__ float g_WcatT[KPAD * NGI];
__device__ float g_gbias[NGI];
__device__ float g_outwT[KX * CC];
__device__ float g_W2[H2 * CIN];
__device__ float g_peB[H2 * LL];
__device__ float g_E[H2 * LL];
__device__ __nv_bfloat16 g_fmh[(long)BB * CIN * LL];
__device__ __nv_bfloat16 g_W2h[H2 * CIN];

__device__ __forceinline__ float ftanh(float x) {
    float y; asm("tanh.approx.f32 %0, %1;" : "=f"(y) : "f"(x)); return y;
}
__device__ __forceinline__ float pe_val(int l, int o) {
    float f = expf((float)(o & ~1) * (-9.210340371976184f / 512.f));
    float a = (float)l * f;
    return (o & 1) ? cosf(a) : sinf(a);
}
__device__ __forceinline__ uint32_t s2u(const void* p) {
    return (uint32_t)__cvta_generic_to_shared(p);
}
__device__ __forceinline__ void ldsm4(uint32_t* r, uint32_t a) {
    asm volatile("ldmatrix.sync.aligned.m8n8.x4.shared.b16 {%0,%1,%2,%3}, [%4];"
                 : "=r"(r[0]), "=r"(r[1]), "=r"(r[2]), "=r"(r[3]) : "r"(a));
}
__device__ __forceinline__ void ldsm4t(uint32_t* r, uint32_t a) {
    asm volatile("ldmatrix.sync.aligned.m8n8.x4.trans.shared.b16 {%0,%1,%2,%3}, [%4];"
                 : "=r"(r[0]), "=r"(r[1]), "=r"(r[2]), "=r"(r[3]) : "r"(a));
}
__device__ __forceinline__ void mma_bf16(float* d, const uint32_t* a, const uint32_t* b) {
    asm volatile(
        "mma.sync.aligned.m16n8k16.row.col.f32.bf16.bf16.f32 "
        "{%0,%1,%2,%3}, {%4,%5,%6,%7}, {%8,%9}, {%0,%1,%2,%3};\n"
        : "+f"(d[0]), "+f"(d[1]), "+f"(d[2]), "+f"(d[3])
        : "r"(a[0]), "r"(a[1]), "r"(a[2]), "r"(a[3]), "r"(b[0]), "r"(b[1]));
}

// ---------------- prep ----------------
__global__ void prep_kernel(const float* __restrict__ wih, const float* __restrict__ whh,
                            const float* __restrict__ bih, const float* __restrict__ bhh,
                            const float* __restrict__ outw, const float* __restrict__ convw,
                            const float* __restrict__ convb) {
    const long R1 = (long)KPAD * NGI;
    const long R2 = R1 + NGI;
    const long R3 = R2 + (long)KX * CC;
    const long R4 = R3 + 256L * CIN;
    const long R5 = R4 + (long)H2 * LL;
    const long R6 = R5 + 256L * LL;
    const long ZTOT = 2L*BB*HH + BB*LL + BB*HH + BB*KPAD;
    const long TOTAL = R6 + ZTOT;
    for (long idx = (long)blockIdx.x * blockDim.x + threadIdx.x; idx < TOTAL;
         idx += (long)gridDim.x * blockDim.x) {
        long i = idx;
        if (i < R1) {
            int k = (int)(i >> 10), j = (int)(i & 1023);
            float v = 0.f;
            if (k < KCAT) {
                if (j < 768) {
                    if (k < KX) v = wih[j * KX + k];
                    else if (j < 512) v = whh[j * HH + (k - KX)];
                } else {
                    if (k >= KX) v = whh[(j - 768 + 512) * HH + (k - KX)];
                }
            }
            g_WcatT[i] = v; continue;
        }
        if (i < R2) { int j = (int)(i - R1);
            g_gbias[j] = (j < 512) ? bih[j] + bhh[j] : (j < 768) ? bih[j] : bhh[j - 256];
            continue; }
        if (i < R3) { long p = i - R2; int k = (int)(p / CC), c = (int)(p % CC);
            g_outwT[p] = outw[c * KX + k]; continue; }
        if (i < R4) { long p = i - R3; g_W2[p] = convw[p]; continue; }
        if (i < R5) { long p = i - R4; int o = (int)(p >> 10), l = (int)(p & 1023);
            g_peB[p] = pe_val(l, o) + convb[o]; continue; }
        if (i < R6) { long p = i - R5; int m = (int)(p >> 10), l = (int)(p & 1023);
            g_E[p] = convb[m] + pe_val(l, m); continue; }
        long p = i - R6;
        if (p < 2L*BB*HH) { g_h[p] = 0.f; continue; } p -= 2L*BB*HH;
        if (p < BB*LL) { g_cov[p] = 0.f; continue; } p -= BB*LL;
        if (p < BB*HH) { g_context[p] = 0.f; continue; } p -= BB*HH;
        g_xcat[p] = 0.f;
    }
}

// ---------------- fp32 -> bf16 conversion ----------------
__global__ void cvt_kernel(const float* __restrict__ fm) {
    const long N1 = (long)BB * CIN * LL / 4;
    const long N2 = (long)H2 * CIN / 4;
    __nv_bfloat162* fo = (__nv_bfloat162*)g_fmh;
    __nv_bfloat162* wo = (__nv_bfloat162*)g_W2h;
    for (long i = (long)blockIdx.x * blockDim.x + threadIdx.x; i < N1 + N2;
         i += (long)gridDim.x * blockDim.x) {
        if (i < N1) {
            float4 v = ((const float4*)fm)[i];
            fo[2 * i]     = __floats2bfloat162_rn(v.x, v.y);
            fo[2 * i + 1] = __floats2bfloat162_rn(v.z, v.w);
        } else {
            long j = i - N1;
            float4 v = ((const float4*)g_W2)[j];
            wo[2 * j]     = __floats2bfloat162_rn(v.x, v.y);
            wo[2 * j + 1] = __floats2bfloat162_rn(v.z, v.w);
        }
    }
}

// ---------------- SIMT SGEMM (small prep GEMMs only) ----------------
__global__ __launch_bounds__(256, 2) void sgemm_kernel(
    const float* __restrict__ A, const float* __restrict__ Bg, float* __restrict__ Cg,
    int M, int N, int K, const float* __restrict__ bias) {
    const int bx = blockIdx.x, by = blockIdx.y, b = blockIdx.z;
    const float* Bp = Bg + (long)b * K * N;
    float* Cp = Cg + (long)b * M * N;
    const int tid = threadIdx.x;
    __shared__ float As[8][128];
    __shared__ float Bs[8][128];
    float acc[8][8];
#pragma unroll
    for (int i = 0; i < 8; i++)
#pragma unroll
        for (int j = 0; j < 8; j++) acc[i][j] = 0.f;
    const int m0 = by * 128, n0 = bx * 128;
    const int arow = tid >> 1, acol = (tid & 1) * 4;
    const int brow = tid >> 5, bcol = (tid & 31) * 4;
    const int ty = tid >> 4, tx = tid & 15;
    for (int k0 = 0; k0 < K; k0 += 8) {
        float4 a4 = *(const float4*)&A[(long)(m0 + arow) * K + k0 + acol];
        As[acol + 0][arow] = a4.x; As[acol + 1][arow] = a4.y;
        As[acol + 2][arow] = a4.z; As[acol + 3][arow] = a4.w;
        *(float4*)&Bs[brow][bcol] = *(const float4*)&Bp[(long)(k0 + brow) * N + n0 + bcol];
        __syncthreads();
#pragma unroll
        for (int kk = 0; kk < 8; kk++) {
            float ra[8], rb[8];
#pragma unroll
            for (int i = 0; i < 8; i++) ra[i] = As[kk][ty * 8 + i];
#pragma unroll
            for (int j = 0; j < 8; j++) rb[j] = Bs[kk][tx * 8 + j];
#pragma unroll
            for (int i = 0; i < 8; i++)
#pragma unroll
                for (int j = 0; j < 8; j++) acc[i][j] = fmaf(ra[i], rb[j], acc[i][j]);
        }
        __syncthreads();
    }
#pragma unroll
    for (int i = 0; i < 8; i++) {
        int m = m0 + ty * 8 + i;
        float bia = bias ? bias[m] : 0.f;
#pragma unroll
        for (int j = 0; j < 8; j++)
            Cp[(long)m * N + n0 + tx * 8 + j] = acc[i][j] + bia;
    }
}

// ---------------- bf16 tensor-core main GEMM, bf16 output ----------------
// Fh[b](512x1024) = bf16( W2h @ fmh[b] + E )
__global__ __launch_bounds__(256, 2) void mma_gemm_kernel(
    const __nv_bfloat16* __restrict__ A, const __nv_bfloat16* __restrict__ Bg,
    __nv_bfloat16* __restrict__ Cg, const float* __restrict__ Etab) {
    const int tid = threadIdx.x;
    const int bx = blockIdx.x, by = blockIdx.y, b = blockIdx.z;
    const __nv_bfloat16* Bp = Bg + (long)b * GK * GN;
    __nv_bfloat16* Cp = Cg + (long)b * GM * GN;
    __shared__ __nv_bfloat16 As[128][40];
    __shared__ __nv_bfloat16 Bs[32][136];
    const int w = tid >> 5, lane = tid & 31;
    const int wm = (w & 3) * 32, wn = (w >> 2) * 64;
    const int m0 = by * 128, n0 = bx * 128;
    const int lg = lane >> 2, lk = lane & 3;

    float acc[2][8][4];
#pragma unroll
    for (int i = 0; i < 2; i++)
#pragma unroll
        for (int j = 0; j < 8; j++)
#pragma unroll
            for (int c = 0; c < 4; c++) acc[i][j][c] = 0.f;

    const int ar = tid >> 1, ac = (tid & 1) * 16;
    const int br = tid >> 3, bc = (tid & 7) * 16;
    const uint32_t aAddr0 = s2u(&As[wm + (lane & 15)][(lane >> 4) * 8]);
    const uint32_t bAddr0 = s2u(&Bs[lane & 15][wn + (lane >> 4) * 8]);

    uint4 ra0, ra1, rb0, rb1;
    {
        const uint4* pa = (const uint4*)(A + (long)(m0 + ar) * GK + ac);
        const uint4* pb = (const uint4*)(Bp + (long)br * GN + n0 + bc);
        ra0 = pa[0]; ra1 = pa[1];
        rb0 = pb[0]; rb1 = pb[1];
    }

    for (int kt = 0; kt < GK / 32; kt++) {
        *(uint4*)&As[ar][ac]     = ra0;
        *(uint4*)&As[ar][ac + 8] = ra1;
        *(uint4*)&Bs[br][bc]     = rb0;
        *(uint4*)&Bs[br][bc + 8] = rb1;
        __syncthreads();
        if (kt + 1 < GK / 32) {
            int k0 = (kt + 1) * 32;
            const uint4* pa = (const uint4*)(A + (long)(m0 + ar) * GK + k0 + ac);
            const uint4* pb = (const uint4*)(Bp + (long)(k0 + br) * GN + n0 + bc);
            ra0 = pa[0]; ra1 = pa[1];
            rb0 = pb[0]; rb1 = pb[1];
        }
#pragma unroll
        for (int ks = 0; ks < 2; ks++) {
            uint32_t af[2][4], bf[4][4];
#pragma unroll
            for (int tm = 0; tm < 2; tm++)
                ldsm4(af[tm], aAddr0 + (tm * 16 * 40 + ks * 16) * 2);
#pragma unroll
            for (int p = 0; p < 4; p++)
                ldsm4t(bf[p], bAddr0 + (ks * 16 * 136 + p * 16) * 2);
#pragma unroll
            for (int tn = 0; tn < 8; tn++) {
                mma_bf16(acc[0][tn], af[0], &bf[tn >> 1][(tn & 1) * 2]);
                mma_bf16(acc[1][tn], af[1], &bf[tn >> 1][(tn & 1) * 2]);
            }
        }
        __syncthreads();
    }
    // epilogue: add E (fp32), convert to bf16x2, store
#pragma unroll
    for (int tm = 0; tm < 2; tm++) {
#pragma unroll
        for (int tn = 0; tn < 8; tn++) {
            int m = m0 + wm + tm * 16 + lg;
            int n = n0 + wn + tn * 8 + 2 * lk;
            long i0 = (long)m * GN + n;
            long i1 = (long)(m + 8) * GN + n;
            float2 e0 = *(const float2*)&Etab[i0];
            float2 e1 = *(const float2*)&Etab[i1];
            *(__nv_bfloat162*)(Cp + i0) =
                __floats2bfloat162_rn(acc[tm][tn][0] + e0.x, acc[tm][tn][1] + e0.y);
            *(__nv_bfloat162*)(Cp + i1) =
                __floats2bfloat162_rn(acc[tm][tn][2] + e1.x, acc[tm][tn][3] + e1.y);
        }
    }
}

// ---------------- K1: gate finalize + out_{t-1} + attention score partials ----------
// compute blocks cx<nch: lchunk = cx&1 (512 l each), hhalf = cx>>1 (128 h each)
__global__ __launch_bounds__(256) void score_kernel(
    int t, int nch,
    const float* __restrict__ count,
    const float* __restrict__ attn_v, const float* __restrict__ attn_vb,
    const float* __restrict__ cov_w, const float* __restrict__ cov_b,
    const float* __restrict__ out_b, float* __restrict__ d_out) {
    const int b = blockIdx.y, cx = blockIdx.x, tid = threadIdx.x;
    float hn = 0.f;
    if (t > 0) {
        const float* gi = g_gi + b * NGI;
        float gr = gi[tid], gz = gi[256 + tid], gin = gi[512 + tid], ghn = gi[768 + tid];
        float hold = g_h[((t - 1) & 1) * BB * HH + b * HH + tid];
        float r = 1.f / (1.f + expf(-gr));
        float z = 1.f / (1.f + expf(-gz));
        float n = tanhf(gin + r * ghn);
        hn = (1.f - z) * n + z * hold;
    }

    if (cx == nch) {  // aux block: write h_t, emit out_{t-1}
        __shared__ float s_x2[640];
        if (t > 0) {
            g_h[(t & 1) * BB * HH + b * HH + tid] = hn;
            s_x2[tid] = hn;
            s_x2[256 + tid] = g_context[b * HH + tid];
            if (tid < CC) s_x2[512 + tid] = count[b * CC + tid];
            __syncthreads();
            if (tid < CC) {
                float acc = out_b[tid];
#pragma unroll 4
                for (int k = 0; k < KX; k++) acc = fmaf(g_outwT[k * CC + tid], s_x2[k], acc);
                d_out[((long)b * TT + (t - 1)) * CC + tid] = acc;
            }
        }
        return;
    }

    const int lchunk = cx & 1, hh0 = (cx >> 1) * 128;
    __shared__ float s_base[128], s_cw[128], s_v[128];
    if (tid < 128) {
        int h = hh0 + tid;
        s_base[tid] = cov_b[h] + ((t > 0) ? g_gi[b * NGI] * 0.f : 0.f);  // placeholder
    }
    // recompute base with correct h-value of hidden: need hn of h index, but hn here is
    // per-tid (tid == h only when tid<... ). Load h_t from the lane that computed it via smem:
    __shared__ float s_hfull[HH];
    s_hfull[tid] = hn;
    __syncthreads();
    if (tid < 128) {
        int h = hh0 + tid;
        s_base[tid] = cov_b[h] + s_hfull[h];
        s_cw[tid] = cov_w[h];
        s_v[tid] = attn_v[h];
    }
    __syncthreads();

    const int p = lchunk * 256 + tid;          // bf16x2 pair index, l = 2p, 2p+1
    const float2 cov = *(const float2*)&g_cov[b * LL + 2 * p];
    const __nv_bfloat162* wf2 =
        (const __nv_bfloat162*)(g_Fh + ((long)b * H2 + 256) * LL) + p;
    float a0 = (hh0 == 0) ? attn_vb[0] : 0.f, a1 = 0.f;
    float b0 = 0.f, b1 = 0.f;
#pragma unroll 4
    for (int hh = 0; hh < 128; hh += 2) {
        float2 w0 = __bfloat1622float2(wf2[(long)(hh0 + hh) * 512]);
        float2 w1 = __bfloat1622float2(wf2[(long)(hh0 + hh + 1) * 512]);
        float ba0 = s_base[hh], cw0 = s_cw[hh], vv0 = s_v[hh];
        float ba1 = s_base[hh + 1], cw1 = s_cw[hh + 1], vv1 = s_v[hh + 1];
        a0 = fmaf(vv0, ftanh(fmaf(cov.x, cw0, w0.x + ba0)), a0);
        a1 = fmaf(vv0, ftanh(fmaf(cov.y, cw0, w0.y + ba0)), a1);
        b0 = fmaf(vv1, ftanh(fmaf(cov.x, cw1, w1.x + ba1)), b0);
        b1 = fmaf(vv1, ftanh(fmaf(cov.y, cw1, w1.y + ba1)), b1);
    }
    *(float2*)&g_scores[(cx >> 1) * BB * LL + b * LL + 2 * p] =
        make_float2(a0 + b0, a1 + b1);
}

// ---------------- K2: softmax + coverage + context + xcat + gi init ----------------
__global__ __launch_bounds__(256) void ctx_kernel(
    int t, const float* __restrict__ count, const int* __restrict__ target,
    const float* __restrict__ emb) {
    const int b = blockIdx.y, c = blockIdx.x, tid = threadIdx.x;
    const int warp = tid >> 5, lane = tid & 31;
    __shared__ float s_alpha[LL];
    __shared__ float s_red[8];

    float4 p0 = ((const float4*)(g_scores + b * LL))[tid];
    float4 p1 = ((const float4*)(g_scores + BB * LL + b * LL))[tid];
    float4 sc = make_float4(p0.x + p1.x, p0.y + p1.y, p0.z + p1.z, p0.w + p1.w);
    float mx = fmaxf(fmaxf(sc.x, sc.y), fmaxf(sc.z, sc.w));
#pragma unroll
    for (int o = 16; o > 0; o >>= 1) mx = fmaxf(mx, __shfl_xor_sync(0xffffffffu, mx, o));
    if (lane == 0) s_red[warp] = mx;
    __syncthreads();
    float M = s_red[0];
#pragma unroll
    for (int w = 1; w < 8; w++) M = fmaxf(M, s_red[w]);
    float e0 = __expf(sc.x - M), e1 = __expf(sc.y - M);
    float e2 = __expf(sc.z - M), e3 = __expf(sc.w - M);
    float sm = e0 + e1 + e2 + e3;
#pragma unroll
    for (int o = 16; o > 0; o >>= 1) sm += __shfl_xor_sync(0xffffffffu, sm, o);
    __syncthreads();
    if (lane == 0) s_red[warp] = sm;
    __syncthreads();
    float S = 0.f;
#pragma unroll
    for (int w = 0; w < 8; w++) S += s_red[w];
    float inv = 1.f / S;
    float4 al = make_float4(e0 * inv, e1 * inv, e2 * inv, e3 * inv);
    ((float4*)s_alpha)[tid] = al;
    if (c == 0) {
        float4 cv = ((float4*)(g_cov + b * LL))[tid];
        cv.x += al.x; cv.y += al.y; cv.z += al.z; cv.w += al.w;
        ((float4*)(g_cov + b * LL))[tid] = cv;
    }
    __syncthreads();

    // context rows d = c*32 .. c*32+31 (each warp 4 rows), bf16 feats
    const __nv_bfloat16* fb = g_Fh + (long)b * H2 * LL;
#pragma unroll
    for (int r = 0; r < 4; r++) {
        int d = c * 32 + warp * 4 + r;
        const uint4* row = (const uint4*)(fb + (long)d * LL);   // 8 bf16 per uint4
        float sum = 0.f;
#pragma unroll
        for (int it = 0; it < 4; it++) {
            uint4 f8 = row[it * 32 + lane];
            const float4* ap = (const float4*)&s_alpha[(it * 32 + lane) * 8];
            float4 a0 = ap[0], a1 = ap[1];
            float2 f0 = __bfloat1622float2(*(__nv_bfloat162*)&f8.x);
            float2 f1 = __bfloat1622float2(*(__nv_bfloat162*)&f8.y);
            float2 f2 = __bfloat1622float2(*(__nv_bfloat162*)&f8.z);
            float2 f3 = __bfloat1622float2(*(__nv_bfloat162*)&f8.w);
            sum = fmaf(f0.x, a0.x, sum); sum = fmaf(f0.y, a0.y, sum);
            sum = fmaf(f1.x, a0.z, sum); sum = fmaf(f1.y, a0.w, sum);
            sum = fmaf(f2.x, a1.x, sum); sum = fmaf(f2.y, a1.y, sum);
            sum = fmaf(f3.x, a1.z, sum); sum = fmaf(f3.y, a1.w, sum);
        }
#pragma unroll
        for (int o = 16; o > 0; o >>= 1) sum += __shfl_xor_sync(0xffffffffu, sum, o);
        if (lane == 0) {
            g_context[b * HH + d] = sum;
            g_xcat[b * KPAD + 256 + d] = sum;
        }
    }

    if (tid < 128) g_gi[b * NGI + c * 128 + tid] = g_gbias[c * 128 + tid];
    if (c == 1) {
        int y = (t == 0) ? 1 : target[b * TT + (t - 1)];
        g_xcat[b * KPAD + tid] = emb[y * DD + tid];
    }
    if (c == 2 && tid < CC) g_xcat[b * KPAD + 512 + tid] = count[b * CC + tid];
    if (c == 3) g_xcat[b * KPAD + KX + tid] = g_h[(t & 1) * BB * HH + b * HH + tid];
}

// ---------------- K3: GRU gate GEMM (K-split, atomic) ----------------
__global__ __launch_bounds__(256) void gru_gemm_kernel() {
    const int nt = blockIdx.x & 15, ks = blockIdx.x >> 4;
    const int n0 = nt * 64, k0 = ks * 112;
    const int tid = threadIdx.x;
    __shared__ float Xs[8][64];
    __shared__ float Ws[8][64];
    const int ml = tid >> 2, kl = (tid & 3) * 2;
    const int kw = tid >> 5, nn = (tid & 31) * 2;
    const int ty = tid >> 4, tx = tid & 15;
    float acc[4][4];
#pragma unroll
    for (int i = 0; i < 4; i++)
#pragma unroll
        for (int j = 0; j < 4; j++) acc[i][j] = 0.f;

    for (int kt = 0; kt < 14; kt++) {
        const int k = k0 + kt * 8;
        Xs[kl + 0][ml] = g_xcat[ml * KPAD + k + kl + 0];
        Xs[kl + 1][ml] = g_xcat[ml * KPAD + k + kl + 1];
        float2 w2 = *(const float2*)&g_WcatT[(k + kw) * NGI + n0 + nn];
        Ws[kw][nn] = w2.x; Ws[kw][nn + 1] = w2.y;
        __syncthreads();
#pragma unroll
        for (int kk = 0; kk < 8; kk++) {
            float rx[4], rw[4];
#pragma unroll
            for (int i = 0; i < 4; i++) rx[i] = Xs[kk][ty * 4 + i];
#pragma unroll
            for (int j = 0; j < 4; j++) rw[j] = Ws[kk][tx * 4 + j];
#pragma unroll
            for (int i = 0; i < 4; i++)
#pragma unroll
                for (int j = 0; j < 4; j++) acc[i][j] = fmaf(rx[i], rw[j], acc[i][j]);
        }
        __syncthreads();
    }
#pragma unroll
    for (int i = 0; i < 4; i++)
#pragma unroll
        for (int j = 0; j < 4; j++)
            atomicAdd(&g_gi[(ty * 4 + i) * NGI + n0 + tx * 4 + j], acc[i][j]);
}

// ---------------- launch ----------------
extern "C" void kernel_launch(void* const* d_in, const int* in_sizes, int n_in,
                              void* d_out, int out_size) {
    const float* fm      = (const float*)d_in[0];
    const float* count   = (const float*)d_in[1];
    const int*   target  = (const int*)d_in[2];
    const float* conv_w  = (const float*)d_in[3];
    const float* conv_b  = (const float*)d_in[4];
    const float* emb     = (const float*)d_in[5];
    const float* gru_wih = (const float*)d_in[6];
    const float* gru_whh = (const float*)d_in[7];
    const float* gru_bih = (const float*)d_in[8];
    const float* gru_bhh = (const float*)d_in[9];
    const float* attn_w  = (const float*)d_in[10];
    const float* attn_b  = (const float*)d_in[11];
    const float* attn_v  = (const float*)d_in[12];
    const float* attn_vb = (const float*)d_in[13];
    const float* cov_w   = (const float*)d_in[14];
    const float* cov_b   = (const float*)d_in[15];
    const float* out_w   = (const float*)d_in[16];
    const float* out_b   = (const float*)d_in[17];
    float* out = (float*)d_out;

    float *pW2, *pPeB, *pE;
    __nv_bfloat16 *pFh, *pFmh, *pW2h;
    cudaGetSymbolAddress((void**)&pFh, g_Fh);
    cudaGetSymbolAddress((void**)&pW2, g_W2);
    cudaGetSymbolAddress((void**)&pPeB, g_peB);
    cudaGetSymbolAddress((void**)&pE, g_E);
    cudaGetSymbolAddress((void**)&pFmh, g_fmh);
    cudaGetSymbolAddress((void**)&pW2h, g_W2h);

    prep_kernel<<<1024, 256>>>(gru_wih, gru_whh, gru_bih, gru_bhh, out_w, conv_w, conv_b);

    sgemm_kernel<<<dim3(8, 2, 1), 256>>>(attn_w, conv_w, pW2 + 256 * CIN,
                                         256, CIN, H2, nullptr);
    sgemm_kernel<<<dim3(8, 2, 1), 256>>>(attn_w, pPeB, pE + 256 * LL,
                                         256, LL, H2, attn_b);
    cvt_kernel<<<2048, 256>>>(fm);
    mma_gemm_kernel<<<dim3(8, 4, BB), 256>>>(pW2h, pFmh, pFh, pE);

    for (int t = 0; t < TT; t++) {
        score_kernel<<<dim3(5, BB), 256>>>(t, 4, count, attn_v, attn_vb,
                                           cov_w, cov_b, out_b, out);
        ctx_kernel<<<dim3(8, BB), 256>>>(t, count, target, emb);
        gru_gemm_kernel<<<128, 256>>>();
    }
    score_kernel<<<dim3(1, BB), 256>>>(TT, 0, count, attn_v, attn_vb,
                                       cov_w, cov_b, out_b, out);
}